// round 2
// baseline (speedup 1.0000x reference)
#include <cuda_runtime.h>

// ---------------------------------------------------------------------------
// CR8_reg_cond_mul_5: fused per-position MLP cascade.
//   h  = lrelu(BN1(W1 x))          (BN folded into W1,b1 by prep kernel)
//   r  = lrelu(BNr(Wr x))
//   x2 = lrelu(W2c h + b2c)
//   lg = W3c x2 + b3c              (129 outputs: 128 logits + mask channel)
//   mask = lrelu(lg[128]); ind = argmax(lg[0:128]); s = ind>>4
//   y  = lrelu([r;h] @ w2[s] + b2[s])   (256x32)
//   reg = y . w3[ind] + b3[ind]
//   x_real = (ind + reg)/128
// Output: [x_real (131072 f32) | mask (131072 f32)]
// ---------------------------------------------------------------------------

#define NPOS    (16 * 8192)
#define TILE    128
#define STRIDE  132            // 128 + 4 pad, keeps float4 alignment

__device__ float g_W1[128 * 128];
__device__ float g_b1[128];
__device__ float g_Wr[128 * 128];
__device__ float g_br[128];

__device__ __forceinline__ float lrelu(float v) {
    return v >= 0.0f ? v : 0.01f * v;
}

// Fold batch-norm into conv weights: W'[o][c] = W[o][c]*s[o],
// b'[o] = (b[o]-m[o])*s[o] + beta[o],  s[o] = g[o]/sqrt(v[o]+eps)
__global__ void prep_kernel(
    const float* __restrict__ cl1_w, const float* __restrict__ cl1_b,
    const float* __restrict__ g1, const float* __restrict__ bt1,
    const float* __restrict__ m1, const float* __restrict__ v1,
    const float* __restrict__ reg_w, const float* __restrict__ reg_b,
    const float* __restrict__ gr, const float* __restrict__ btr,
    const float* __restrict__ mr, const float* __restrict__ vr)
{
    int idx = blockIdx.x * blockDim.x + threadIdx.x;
    if (idx < 128 * 128) {
        int o = idx >> 7;
        float s1 = g1[o] * rsqrtf(v1[o] + 1e-5f);
        float sr = gr[o] * rsqrtf(vr[o] + 1e-5f);
        g_W1[idx] = cl1_w[idx] * s1;
        g_Wr[idx] = reg_w[idx] * sr;
        if (idx < 128) {
            int oo = idx;
            float ss1 = g1[oo] * rsqrtf(v1[oo] + 1e-5f);
            float ssr = gr[oo] * rsqrtf(vr[oo] + 1e-5f);
            g_b1[oo] = (cl1_b[oo] - m1[oo]) * ss1 + bt1[oo];
            g_br[oo] = (reg_b[oo] - mr[oo]) * ssr + btr[oo];
        }
    }
}

// 128x128x128 GEMM: Cs[o][p] = act(sum_k W[o][k]*Bs[k][p] + bias[o])
// W from global memory ([O][128] row-major), Bs/Cs in smem (STRIDE-pitched).
// Safe for Cs == Bs (barrier before epilogue writes).
__device__ __forceinline__ void gemm128(
    const float* __restrict__ W, const float* __restrict__ bias,
    const float* Bs, float* Cs, float* Wt, int tid, bool relu)
{
    const int ty = tid >> 4, tx = tid & 15;
    const int o0 = ty * 8, p0 = tx * 8;

    float acc[8][8];
#pragma unroll
    for (int i = 0; i < 8; ++i)
#pragma unroll
        for (int j = 0; j < 8; ++j) acc[i][j] = 0.0f;

    for (int kc = 0; kc < 8; ++kc) {
        __syncthreads();
        // stage W chunk transposed: Wt[k][o] = W[o][kc*16+k], k in [0,16)
        {
            int base = tid * 8;
            int k0 = base & 15;          // 0 or 8
            int o  = base >> 4;          // 0..127
            const float* src = &W[o * 128 + kc * 16 + k0];
            float4 v0 = *(const float4*)(src);
            float4 v1 = *(const float4*)(src + 4);
            Wt[(k0 + 0) * STRIDE + o] = v0.x;
            Wt[(k0 + 1) * STRIDE + o] = v0.y;
            Wt[(k0 + 2) * STRIDE + o] = v0.z;
            Wt[(k0 + 3) * STRIDE + o] = v0.w;
            Wt[(k0 + 4) * STRIDE + o] = v1.x;
            Wt[(k0 + 5) * STRIDE + o] = v1.y;
            Wt[(k0 + 6) * STRIDE + o] = v1.z;
            Wt[(k0 + 7) * STRIDE + o] = v1.w;
        }
        __syncthreads();
#pragma unroll
        for (int k = 0; k < 16; ++k) {
            float4 a0 = *(const float4*)&Wt[k * STRIDE + o0];
            float4 a1 = *(const float4*)&Wt[k * STRIDE + o0 + 4];
            const float* br = &Bs[(kc * 16 + k) * STRIDE + p0];
            float4 b0 = *(const float4*)(br);
            float4 b1 = *(const float4*)(br + 4);
            float a[8] = {a0.x, a0.y, a0.z, a0.w, a1.x, a1.y, a1.z, a1.w};
            float bb[8] = {b0.x, b0.y, b0.z, b0.w, b1.x, b1.y, b1.z, b1.w};
#pragma unroll
            for (int i = 0; i < 8; ++i)
#pragma unroll
                for (int j = 0; j < 8; ++j)
                    acc[i][j] = fmaf(a[i], bb[j], acc[i][j]);
        }
    }
    __syncthreads();   // all Bs reads done -> safe even when Cs aliases Bs
#pragma unroll
    for (int i = 0; i < 8; ++i) {
        float bi = bias[o0 + i];
#pragma unroll
        for (int j = 0; j < 8; ++j) {
            float v = acc[i][j] + bi;
            if (relu) v = lrelu(v);
            Cs[(o0 + i) * STRIDE + p0 + j] = v;
        }
    }
}

__global__ void __launch_bounds__(256, 1)
main_kernel(const float* __restrict__ x_in,
            const float* __restrict__ cl2_w, const float* __restrict__ cl2_b,
            const float* __restrict__ cl3_w, const float* __restrict__ cl3_b,
            const float* __restrict__ w2,    const float* __restrict__ b2,
            const float* __restrict__ w3,    const float* __restrict__ b3,
            float* __restrict__ out)
{
    extern __shared__ float smem[];
    float* Xs    = smem;                       // 128*STRIDE  (X, then X2, then logits)
    float* Hs    = Xs + 128 * STRIDE;          // 128*STRIDE
    float* Rs    = Hs + 128 * STRIDE;          // 128*STRIDE
    float* Wt    = Rs + 128 * STRIDE;          // 16*STRIDE
    float* maskv = Wt + 16 * STRIDE;           // 128
    int*   inds  = (int*)(maskv + 128);        // 128
    int*   perm  = inds + 128;                 // 128
    int*   cnt   = perm + 128;                 // 16 (counts + offsets)

    const int tid  = threadIdx.x;
    const int tile = blockIdx.x;               // 0..1023
    const int b    = tile >> 6;                // 64 tiles per batch image
    const int w0   = (tile & 63) * TILE;
    const float* xb = x_in + (size_t)b * 128 * 8192 + w0;

    // ---- load X tile: Xs[c][w] -------------------------------------------
#pragma unroll
    for (int i = 0; i < 64; ++i) {
        int idx = i * 256 + tid;
        int c = idx >> 7, w = idx & 127;
        Xs[c * STRIDE + w] = xb[c * 8192 + w];
    }

    // ---- dense cascade ----------------------------------------------------
    gemm128(g_W1, g_b1, Xs, Hs, Wt, tid, true);   // h
    gemm128(g_Wr, g_br, Xs, Rs, Wt, tid, true);   // r   (Xs dead after this)
    gemm128(cl2_w, cl2_b, Hs, Xs, Wt, tid, true); // x2 -> Xs
    __syncthreads();

    // ---- mask channel (row 128 of cl3) before logits clobber Xs ----------
    if (tid < 128) {
        int w = tid;
        float m = cl3_b[128];
        const float* wrow = cl3_w + 128 * 128;
#pragma unroll 8
        for (int c = 0; c < 128; ++c)
            m = fmaf(wrow[c], Xs[c * STRIDE + w], m);
        maskv[w] = lrelu(m);
    }

    gemm128(cl3_w, cl3_b, Xs, Xs, Wt, tid, false); // logits (in place)
    __syncthreads();

    // ---- argmax over 128 logits per position -----------------------------
    if (tid < 128) {
        int w = tid;
        float best = Xs[w];
        int bi = 0;
#pragma unroll 8
        for (int o = 1; o < 128; ++o) {
            float v = Xs[o * STRIDE + w];
            if (v > best) { best = v; bi = o; }
        }
        inds[w] = bi;
    }
    if (tid < 16) cnt[tid] = 0;
    __syncthreads();

    // ---- counting sort by super (improves w2 gather coherence) -----------
    if (tid < 128) atomicAdd(&cnt[inds[tid] >> 4], 1);
    __syncthreads();
    if (tid == 0) {
        int run = 0;
#pragma unroll
        for (int s = 0; s < 8; ++s) { cnt[8 + s] = run; run += cnt[s]; }
    }
    __syncthreads();
    if (tid < 128) {
        int s = inds[tid] >> 4;
        int p = atomicAdd(&cnt[8 + s], 1);
        perm[p] = tid;
    }
    __syncthreads();

    // ---- gathered 256x32 GEMV + final regression --------------------------
    // 2 threads per position: t2=0 handles r-half, t2=1 handles h-half.
    {
        const int pr = tid >> 1, t2 = tid & 1;
        const int w = perm[pr];
        const int ind = inds[w];
        const int s = ind >> 4;
        const float* buf = t2 ? Hs : Rs;
        const float* w2p = w2 + ((size_t)s * 256 + (size_t)t2 * 128) * 32;

        float acc[32];
#pragma unroll
        for (int o = 0; o < 32; ++o) acc[o] = 0.0f;

#pragma unroll 2
        for (int f = 0; f < 128; ++f) {
            float v = buf[f * STRIDE + w];
            const float4* wr = (const float4*)(w2p + f * 32);
#pragma unroll
            for (int q = 0; q < 8; ++q) {
                float4 t = wr[q];
                acc[q * 4 + 0] = fmaf(v, t.x, acc[q * 4 + 0]);
                acc[q * 4 + 1] = fmaf(v, t.y, acc[q * 4 + 1]);
                acc[q * 4 + 2] = fmaf(v, t.z, acc[q * 4 + 2]);
                acc[q * 4 + 3] = fmaf(v, t.w, acc[q * 4 + 3]);
            }
        }
        // combine the two halves (adjacent lanes)
#pragma unroll
        for (int o = 0; o < 32; ++o)
            acc[o] += __shfl_xor_sync(0xFFFFFFFFu, acc[o], 1);

        float reg = b3[ind];
        const float* b2p = b2 + s * 32;
        const float* w3p = w3 + ind * 32;
#pragma unroll
        for (int o = 0; o < 32; ++o) {
            float y = lrelu(acc[o] + b2p[o]);
            reg = fmaf(y, w3p[o], reg);
        }
        if (t2 == 0) {
            int n = b * 8192 + w0 + w;
            out[n] = ((float)ind + reg) * (1.0f / 128.0f);
            out[NPOS + n] = maskv[w];
        }
    }
}

// ---------------------------------------------------------------------------

static const size_t SMEM_BYTES =
    (size_t)(3 * 128 * STRIDE + 16 * STRIDE + 128) * sizeof(float)
    + (size_t)(128 + 128 + 16) * sizeof(int);

extern "C" void kernel_launch(void* const* d_in, const int* in_sizes, int n_in,
                              void* d_out, int out_size)
{
    const float* x_in   = (const float*)d_in[0];
    const float* cl1_w  = (const float*)d_in[1];
    const float* cl1_b  = (const float*)d_in[2];
    const float* cl1_g  = (const float*)d_in[3];
    const float* cl1_bt = (const float*)d_in[4];
    const float* cl1_m  = (const float*)d_in[5];
    const float* cl1_v  = (const float*)d_in[6];
    const float* cl2_w  = (const float*)d_in[7];
    const float* cl2_b  = (const float*)d_in[8];
    const float* cl3_w  = (const float*)d_in[9];
    const float* cl3_b  = (const float*)d_in[10];
    const float* reg1_w = (const float*)d_in[11];
    const float* reg1_b = (const float*)d_in[12];
    const float* reg1_g = (const float*)d_in[13];
    const float* reg1_bt= (const float*)d_in[14];
    const float* reg1_m = (const float*)d_in[15];
    const float* reg1_v = (const float*)d_in[16];
    const float* w2     = (const float*)d_in[17];
    const float* b2     = (const float*)d_in[18];
    const float* w3     = (const float*)d_in[19];
    const float* b3     = (const float*)d_in[20];
    float* out = (float*)d_out;

    cudaFuncSetAttribute(main_kernel,
                         cudaFuncAttributeMaxDynamicSharedMemorySize,
                         (int)SMEM_BYTES);

    prep_kernel<<<64, 256>>>(cl1_w, cl1_b, cl1_g, cl1_bt, cl1_m, cl1_v,
                             reg1_w, reg1_b, reg1_g, reg1_bt, reg1_m, reg1_v);
    main_kernel<<<1024, 256, SMEM_BYTES>>>(x_in, cl2_w, cl2_b, cl3_w, cl3_b,
                                           w2, b2, w3, b3, out);
}